// round 13
// baseline (speedup 1.0000x reference)
#include <cuda_runtime.h>

#define HH    512
#define WW    512
#define HW    (HH * WW)
#define NKW   32
#define NK    1024
#define BATCH 64

// Init: out[b,n] = bias[n], vectorized. Full overwrite -> replay idempotent.
__global__ __launch_bounds__(256) void bslc_init(
    const float4* __restrict__ bias4, float4* __restrict__ out4)
{
    const int idx = blockIdx.x * 256 + threadIdx.x;   // 16384 float4 slots
    out4[idx] = bias4[idx & 255];
}

static __device__ __forceinline__ float4 f4add(float4 a, float4 b) {
    return make_float4(a.x + b.x, a.y + b.y, a.z + b.z, a.w + b.w);
}

// Aligned-scatter kernel, batch-packed reduction.
// Block = one 32px x 16row aligned region (g,k) of the ACTUAL image
// (padding never touched). All 64 batches per block (weights read once).
// Geometry identical to the verified R12 kernel:
//   pixel (y,x): windows rows cy-1+wr', cols 2k-1+cxo+wc'
//   cy = g + (qr>>1), cxo = (f+2)>>2, dy = y+8-16*wrow, dx = xcol+8-16*wcol.
//
// Per 4-batch pass: 4 fully-aligned LDG.128 (4 wavefronts each), 16 FMA per
// batch, then the lane's 4 (wr,wc) partials are packed ACROSS BATCHES into
// float4 -> 4 STS.128/thread (was 16 scalar STS). Reduction: stage A sums
// over r (4 contiguous float4 per thread); stage B sums f-ranges/qr-sets
// per window and fires 4 spread atomicAdds into bias-initialized out.
__global__ __launch_bounds__(256, 4) void bslc_main(
    const float* __restrict__ x,       // (64,1,512,512)
    const float* __restrict__ weight,  // (NK,1024)
    float* __restrict__ out)           // (64,NK) = bias-initialized
{
    // components of each float4 = the 4 batches of the pass
    __shared__ __align__(16) float4 sred[2][2][2][4][32]; // [bs][wr][wc][qr][4f+r] 16KB
    __shared__ __align__(16) float4 stA [2][2][2][4][8];  // [bs][wr][wc][qr][f]    4KB

    const int g = blockIdx.x >> 4;     // row-group 0..31
    const int k = blockIdx.x & 15;     // col-span  0..15
    const int tid  = threadIdx.x;
    const int lane = tid & 31;
    const int warp = tid >> 5;
    const int qr = warp >> 1;          // 4-row band 0..3
    const int bs = warp & 1;           // batch half

    const int f = lane & 7;            // float4 quad in 128B row
    const int r = lane >> 3;           // row within band
    const int slot = f * 4 + r;        // f-major slots: f-ranges contiguous

    const int cxo  = (f + 2) >> 2;     // 0,1,2
    const int y    = 16 * g + 4 * qr + r;
    const int xcol = 32 * k + 4 * f;
    const int cy   = g + (qr >> 1);

    // Lane's 4 weight float4s (wr' x wc'), zero for invalid windows
    float4 w[2][2];
#pragma unroll
    for (int wr = 0; wr < 2; wr++)
#pragma unroll
        for (int wc = 0; wc < 2; wc++) {
            const int wrow = cy - 1 + wr;
            const int wcol = 2 * k - 1 + cxo + wc;
            float4 ww = make_float4(0.f, 0.f, 0.f, 0.f);
            if (wrow >= 0 && wrow < 32 && wcol >= 0 && wcol < 32) {
                const int dy = y    + 8 - 16 * wrow;
                const int dx = xcol + 8 - 16 * wcol;
                ww = *reinterpret_cast<const float4*>(
                        weight + (wrow * NKW + wcol) * 1024 + dy * 32 + dx);
            }
            w[wr][wc] = ww;
        }

    const float* __restrict__ xb =
        x + (size_t)(bs * 32) * HW + y * WW + xcol;

    for (int pass = 0; pass < 8; pass++) {
        // 4 aligned LDG.128 (4 full 128B lines each -> 4 wavefronts)
        float4 xv[4];
#pragma unroll
        for (int bp = 0; bp < 4; bp++)
            xv[bp] = *reinterpret_cast<const float4*>(
                         xb + (size_t)(pass * 4 + bp) * HW);

        // Pack partials across batches: one STS.128 per (wr,wc)
#pragma unroll
        for (int wr = 0; wr < 2; wr++)
#pragma unroll
            for (int wc = 0; wc < 2; wc++) {
                const float4 ww = w[wr][wc];
                float4 v;
                v.x = fmaf(xv[0].x, ww.x, fmaf(xv[0].y, ww.y,
                      fmaf(xv[0].z, ww.z, xv[0].w * ww.w)));
                v.y = fmaf(xv[1].x, ww.x, fmaf(xv[1].y, ww.y,
                      fmaf(xv[1].z, ww.z, xv[1].w * ww.w)));
                v.z = fmaf(xv[2].x, ww.x, fmaf(xv[2].y, ww.y,
                      fmaf(xv[2].z, ww.z, xv[2].w * ww.w)));
                v.w = fmaf(xv[3].x, ww.x, fmaf(xv[3].y, ww.y,
                      fmaf(xv[3].z, ww.z, xv[3].w * ww.w)));
                sred[bs][wr][wc][qr][slot] = v;   // contiguous 512B/warp
            }
        __syncthreads();

        // Stage A: 256 threads, sum over r (4 contiguous float4 each)
        {
            const int f2  = tid & 7;
            const int qr2 = (tid >> 3) & 3;
            const int wc2 = (tid >> 5) & 1;
            const int wr2 = (tid >> 6) & 1;
            const int bs2 = tid >> 7;
            const float4* p = &sred[bs2][wr2][wc2][qr2][f2 * 4];
            const float4 a = f4add(f4add(p[0], p[1]), f4add(p[2], p[3]));
            stA[bs2][wr2][wc2][qr2][f2] = a;
        }
        __syncthreads();

        // Stage B: 24 threads -> (bs3, window-row j, window-col wci)
        if (tid < 24) {
            const int wci  = tid & 3;
            const int rest = tid >> 2;       // 0..5
            const int j    = rest % 3;
            const int bs3  = rest / 3;

            // f-quad ranges (same table as the verified R12 kernel)
            const int l0 = (wci == 0) ? 0 : (wci == 1) ? 2 : (wci == 2) ? 6 : 8;
            const int h0 = (wci == 0) ? 2 : (wci == 1) ? 6 : (wci == 2) ? 8 : 8;
            const int l1 = (wci == 0) ? 8 : (wci == 1) ? 0 : (wci == 2) ? 2 : 6;
            const int h1 = (wci == 0) ? 8 : (wci == 1) ? 2 : (wci == 2) ? 6 : 8;

            float4 acc = make_float4(0.f, 0.f, 0.f, 0.f);
#pragma unroll
            for (int qq = 0; qq < 4; qq++) {
                const int wr3 = j - (qq >> 1);
                if (wr3 == 0 || wr3 == 1) {
                    const float4* a0 = &stA[bs3][wr3][0][qq][0];
                    const float4* a1 = &stA[bs3][wr3][1][qq][0];
#pragma unroll 1
                    for (int i = l0; i < h0; i++) acc = f4add(acc, a0[i]);
#pragma unroll 1
                    for (int i = l1; i < h1; i++) acc = f4add(acc, a1[i]);
                }
            }

            const int wrow = g - 1 + j;
            const int wcol = 2 * k - 1 + wci;
            if (wrow >= 0 && wrow < 32 && wcol >= 0 && wcol < 32) {
                const int bbase = bs3 * 32 + pass * 4;
                float* o = out + (size_t)wrow * NKW + wcol;
                atomicAdd(o + (size_t)(bbase + 0) * NK, acc.x);
                atomicAdd(o + (size_t)(bbase + 1) * NK, acc.y);
                atomicAdd(o + (size_t)(bbase + 2) * NK, acc.z);
                atomicAdd(o + (size_t)(bbase + 3) * NK, acc.w);
            }
        }
        // No third barrier needed: next-pass STS (sred) is safe because
        // stage-A reads finished before the second barrier; stage-B reads
        // stA, which is only rewritten after the NEXT first barrier.
        __syncthreads();
    }
}

extern "C" void kernel_launch(void* const* d_in, const int* in_sizes, int n_in,
                              void* d_out, int out_size)
{
    const float* x      = (const float*)d_in[0];   // (64,1,512,512) fp32
    const float* weight = (const float*)d_in[1];   // (1024,1024)    fp32
    const float* bias   = (const float*)d_in[2];   // (1024,)        fp32
    float*       out    = (float*)d_out;           // (64,32,32)     fp32

    bslc_init<<<(BATCH * NK) / (256 * 4), 256>>>(
        (const float4*)bias, (float4*)out);

    bslc_main<<<32 * 16, 256>>>(x, weight, out);   // 512 aligned regions
}

// round 14
// speedup vs baseline: 1.7832x; 1.7832x over previous
#include <cuda_runtime.h>

#define HH    512
#define WW    512
#define HW    (HH * WW)
#define NKW   32
#define NK    1024
#define BATCH 64

// Init: out[b,n] = bias[n], vectorized. Full overwrite -> replay idempotent.
__global__ __launch_bounds__(256) void bslc_init(
    const float4* __restrict__ bias4, float4* __restrict__ out4)
{
    const int idx = blockIdx.x * 256 + threadIdx.x;   // 16384 float4 slots
    out4[idx] = bias4[idx & 255];
}

static __device__ __forceinline__ float4 f4add(float4 a, float4 b) {
    return make_float4(a.x + b.x, a.y + b.y, a.z + b.z, a.w + b.w);
}
static __device__ __forceinline__ float dot4(float4 a, float4 b) {
    return fmaf(a.x, b.x, fmaf(a.y, b.y, fmaf(a.z, b.z, a.w * b.w)));
}

// Aligned-scatter kernel (verified R12 geometry), lean packed reduction.
// Block = (32px x 16row aligned region (g,k), batch half of 32).
// grid = 512 x 2 -> 1024 blocks (~1.7 waves) ; weights read 2x total.
//
// Geometry (identical to the twice-verified R12 kernel):
//   pixel (y,x): y=16g+4qr+r, xcol=32k+4f ; cy=g+(qr>>1), cxo=(f+2)>>2
//   windows: wrow=cy-1+wr', wcol=2k-1+cxo+wc' ; dy=y+8-16wrow, dx=xcol+8-16wcol
//
// Warp = (qr band, bs 16-batch half). 4 passes of 4 batches:
//   4 fully-aligned LDG.128 (4 wavefronts each, optimal), partials packed
//   across batches -> 4 STS.128/thread (slot == lane, conflict-free).
// Stage A (128 thr): sum r and the qr-pair -> 8 LDS.128 at 128B lane stride
//   (conflict-free). Stage B (24 thr): <=12 LDS per window task, 4 spread
//   atomicAdds into bias-initialized out; runs while other warps prefetch.
__global__ __launch_bounds__(256, 4) void bslc_main(
    const float* __restrict__ x,       // (64,1,512,512)
    const float* __restrict__ weight,  // (NK,1024)
    float* __restrict__ out)           // (64,NK) = bias-initialized
{
    __shared__ __align__(16) float4 sred[2][2][2][4][32]; // [bs][wr][wc][qr][lane] 16KB
    __shared__ __align__(16) float4 stA [2][2][2][2][8];  // [bs][wr][wc][pr][f]    2KB

    const int g = blockIdx.x >> 4;     // row-group 0..31
    const int k = blockIdx.x & 15;     // col-span  0..15
    const int tid  = threadIdx.x;
    const int lane = tid & 31;
    const int warp = tid >> 5;
    const int qr = warp >> 1;          // 4-row band 0..3
    const int bs = warp & 1;           // 16-batch half within block

    const int f = lane & 7;            // float4 quad in the 128B row
    const int r = lane >> 3;           // row within band
    const int cxo  = (f + 2) >> 2;     // 0,1,2
    const int y    = 16 * g + 4 * qr + r;
    const int xcol = 32 * k + 4 * f;
    const int cy   = g + (qr >> 1);

    // Lane's 4 weight float4s (wr' x wc'), zero for invalid windows
    float4 w[2][2];
#pragma unroll
    for (int wr = 0; wr < 2; wr++)
#pragma unroll
        for (int wc = 0; wc < 2; wc++) {
            const int wrow = cy - 1 + wr;
            const int wcol = 2 * k - 1 + cxo + wc;
            float4 ww = make_float4(0.f, 0.f, 0.f, 0.f);
            if (wrow >= 0 && wrow < 32 && wcol >= 0 && wcol < 32) {
                const int dy = y    + 8 - 16 * wrow;
                const int dx = xcol + 8 - 16 * wcol;
                ww = *reinterpret_cast<const float4*>(
                        weight + (wrow * NKW + wcol) * 1024 + dy * 32 + dx);
            }
            w[wr][wc] = ww;
        }

    const int bbase0 = blockIdx.y * 32 + bs * 16;
    const float* __restrict__ xb = x + (size_t)bbase0 * HW + y * WW + xcol;

#pragma unroll
    for (int pass = 0; pass < 4; pass++) {
        // 4 aligned LDG.128 (4 full 128B lines each)
        float4 xv[4];
#pragma unroll
        for (int bp = 0; bp < 4; bp++)
            xv[bp] = *reinterpret_cast<const float4*>(
                         xb + (size_t)(pass * 4 + bp) * HW);

        // Pack partials across the 4 batches: one STS.128 per (wr,wc)
#pragma unroll
        for (int wr = 0; wr < 2; wr++)
#pragma unroll
            for (int wc = 0; wc < 2; wc++) {
                const float4 ww = w[wr][wc];
                const float4 v = make_float4(dot4(xv[0], ww), dot4(xv[1], ww),
                                             dot4(xv[2], ww), dot4(xv[3], ww));
                sred[bs][wr][wc][qr][lane] = v;   // slot == lane
            }
        __syncthreads();

        // Stage A: 128 threads sum rows r and the qr-pair (8 LDS.128 each,
        // 128B lane stride -> conflict-free)
        if (tid < 128) {
            const int f2  = tid & 7;
            const int pr  = (tid >> 3) & 1;
            const int wc2 = (tid >> 4) & 1;
            const int wr2 = (tid >> 5) & 1;
            const int bs2 = (tid >> 6) & 1;
            float4 a = make_float4(0.f, 0.f, 0.f, 0.f);
#pragma unroll
            for (int e = 0; e < 2; e++)
#pragma unroll
                for (int rr = 0; rr < 4; rr++)
                    a = f4add(a, sred[bs2][wr2][wc2][2 * pr + e][rr * 8 + f2]);
            stA[bs2][wr2][wc2][pr][f2] = a;
        }
        __syncthreads();

        // Stage B: 24 threads -> (bs3, window-row j, window-col wci).
        // Other warps legally run ahead into the next pass's loads/STS;
        // stage A(p+1) is gated behind the next barrier, so stA is safe.
        if (tid < 24) {
            const int wci  = tid & 3;
            const int rest = tid >> 2;       // 0..5
            const int j    = rest % 3;
            const int bs3  = rest / 3;

            // f-quad ranges (verified R12 table)
            const int l0 = (wci == 0) ? 0 : (wci == 1) ? 2 : (wci == 2) ? 6 : 8;
            const int h0 = (wci == 0) ? 2 : (wci == 1) ? 6 : (wci == 2) ? 8 : 8;
            const int l1 = (wci == 0) ? 8 : (wci == 1) ? 0 : (wci == 2) ? 2 : 6;
            const int h1 = (wci == 0) ? 8 : (wci == 1) ? 2 : (wci == 2) ? 6 : 8;

            float4 acc = make_float4(0.f, 0.f, 0.f, 0.f);
            // set (pr=0, wr=j): rows half 0 ; valid for j<=1
            if (j <= 1) {
#pragma unroll 1
                for (int i = l0; i < h0; i++) acc = f4add(acc, stA[bs3][j][0][0][i]);
#pragma unroll 1
                for (int i = l1; i < h1; i++) acc = f4add(acc, stA[bs3][j][1][0][i]);
            }
            // set (pr=1, wr=j-1): rows half 1 ; valid for j>=1
            if (j >= 1) {
#pragma unroll 1
                for (int i = l0; i < h0; i++) acc = f4add(acc, stA[bs3][j-1][0][1][i]);
#pragma unroll 1
                for (int i = l1; i < h1; i++) acc = f4add(acc, stA[bs3][j-1][1][1][i]);
            }

            const int wrow = g - 1 + j;
            const int wcol = 2 * k - 1 + wci;
            if (wrow >= 0 && wrow < 32 && wcol >= 0 && wcol < 32) {
                const int bb = blockIdx.y * 32 + bs3 * 16 + pass * 4;
                float* o = out + (size_t)wrow * NKW + wcol;
                atomicAdd(o + (size_t)(bb + 0) * NK, acc.x);
                atomicAdd(o + (size_t)(bb + 1) * NK, acc.y);
                atomicAdd(o + (size_t)(bb + 2) * NK, acc.z);
                atomicAdd(o + (size_t)(bb + 3) * NK, acc.w);
            }
        }
        // no third barrier: next-pass STS targets sred (reads done at bar2);
        // stage-B threads rejoin at the next pass's first barrier.
    }
}

extern "C" void kernel_launch(void* const* d_in, const int* in_sizes, int n_in,
                              void* d_out, int out_size)
{
    const float* x      = (const float*)d_in[0];   // (64,1,512,512) fp32
    const float* weight = (const float*)d_in[1];   // (1024,1024)    fp32
    const float* bias   = (const float*)d_in[2];   // (1024,)        fp32
    float*       out    = (float*)d_out;           // (64,32,32)     fp32

    bslc_init<<<(BATCH * NK) / (256 * 4), 256>>>(
        (const float4*)bias, (float4*)out);

    dim3 grid(32 * 16, 2);                         // region x batch-half
    bslc_main<<<grid, 256>>>(x, weight, out);
}

// round 16
// speedup vs baseline: 2.2121x; 1.2405x over previous
#include <cuda_runtime.h>

#define HH    512
#define WW    512
#define HW    (HH * WW)
#define PAD   8
#define NKH   32
#define NKW   32
#define NK    1024
#define NC    33            // stride cells per dim (528/16)
#define BATCH 64
#define RPAD  36            // padded smem row (words): conflict-free LDS.128

// Init: out[b,n] = bias[n], vectorized. Full overwrite -> replay idempotent.
__global__ __launch_bounds__(256) void bslc_init(
    const float4* __restrict__ bias4, float4* __restrict__ out4)
{
    const int idx = blockIdx.x * 256 + threadIdx.x;   // 16384 float4 slots
    out4[idx] = bias4[idx & 255];
}

// One block per 16x16 stride cell (R6's verified geometry). Cell (Ri,Ci)
// covers padded pixels [16Ri,16Ri+16)x[16Ci,16Ci+16); these feed windows
// (Ri-i,Ci-j), i,j in {0,1}, at kernel offsets (dy+16i,dx+16j), q=i*2+j.
//
// Warp w owns batches 8w..8w+7; lane owns pixel-quads lane and lane+32.
// vs the 16.9us champion, two changes:
//  (1) weights staged ONCE through 4KB smem (one LDG.128/thread) instead of
//      every warp re-loading the same 4KB (35MB -> 4.4MB L2 traffic);
//  (2) depth-2 software pipeline on the x loads (MLP=4).
// Reduction identical: per batch 32 FMA + 4 conflict-free STS; after one
// barrier, thread (b,q) sums its 32-lane row (8 conflict-free LDS.128) and
// fires one atomicAdd into bias-initialized out (4 per (b,n) total).
__global__ __launch_bounds__(256, 4) void bslc_main(
    const float* __restrict__ x,       // (64,1,512,512)
    const float* __restrict__ weight,  // (NK,1024)
    float* __restrict__ out)           // (64,NK) = bias-initialized
{
    __shared__ __align__(16) float4 w_s[2][4][32];        // 4KB staged weights
    __shared__ __align__(16) float  sred[8][8][4][RPAD];  // 36KB partials

    const int cell = blockIdx.x;
    const int Ri = cell / NC, Ci = cell % NC;
    const int tid  = threadIdx.x;
    const int lane = tid & 31;
    const int warp = tid >> 5;

    // Quadrant windows + validity (uniform across block, full 4-sided check)
    int nq[4]; bool vq[4];
#pragma unroll
    for (int q = 0; q < 4; q++) {
        const int r = Ri - (q >> 1), c = Ci - (q & 1);
        vq[q] = (r >= 0) && (r < NKH) && (c >= 0) && (c < NKW);
        nq[q] = vq[q] ? (r * NKW + c) : 0;
    }

    // Cooperative weight stage: warp ws -> (s = ws>>2, q = ws&3); one
    // LDG.128 per thread into w_s[s][q][lane].
    {
        const int s  = warp >> 2;
        const int q  = warp & 3;
        const int dy = (lane >> 2) + 8 * s;
        const int dx = (lane & 3) << 2;
        float4 w = make_float4(0.f, 0.f, 0.f, 0.f);
        if (vq[q])
            w = *reinterpret_cast<const float4*>(
                    weight + nq[q] * 1024
                           + (dy + 16 * (q >> 1)) * 32
                           + (dx + 16 * (q & 1)));
        w_s[s][q][lane] = w;
    }
    __syncthreads();

    // Lane's weights to registers: 8 conflict-free LDS.128
    float4 wreg[2][4];
#pragma unroll
    for (int s = 0; s < 2; s++)
#pragma unroll
        for (int q = 0; q < 4; q++)
            wreg[s][q] = w_s[s][q][lane];

    // Lane's two pixel-quads (verbatim R6 indexing)
    bool ok[2]; int off[2];
#pragma unroll
    for (int s = 0; s < 2; s++) {
        const int dy = (lane >> 2) + 8 * s;
        const int dx = (lane & 3) << 2;
        const int uy = Ri * 16 + dy - PAD;
        const int ux = Ci * 16 + dx - PAD;
        ok[s]  = ((unsigned)uy < (unsigned)HH) &&
                 ((unsigned)ux <= (unsigned)(WW - 4));
        off[s] = uy * WW + ux;
    }

    const int b0 = warp * 8;
    const float* __restrict__ xb = x + (size_t)b0 * HW;

#define LDX(t, s) ( ok[s] ? *reinterpret_cast<const float4*>( \
                        xb + (size_t)(t) * HW + off[s])        \
                          : make_float4(0.f, 0.f, 0.f, 0.f) )

    // Depth-2 pipeline over the 8 batches (MLP = 4)
    float4 c0 = LDX(0, 0), c1 = LDX(0, 1);
    float4 n0 = LDX(1, 0), n1 = LDX(1, 1);

#pragma unroll
    for (int t = 0; t < 8; t++) {
        float4 p0, p1;
        if (t + 2 < 8) { p0 = LDX(t + 2, 0); p1 = LDX(t + 2, 1); }

#pragma unroll
        for (int q = 0; q < 4; q++) {
            float s;
            s = fmaf(c0.x, wreg[0][q].x,
                fmaf(c0.y, wreg[0][q].y,
                fmaf(c0.z, wreg[0][q].z, c0.w * wreg[0][q].w)));
            s = fmaf(c1.x, wreg[1][q].x,
                fmaf(c1.y, wreg[1][q].y,
                fmaf(c1.z, wreg[1][q].z, fmaf(c1.w, wreg[1][q].w, s))));
            sred[warp][t][q][lane] = s;        // conflict-free STS.32
        }

        c0 = n0; c1 = n1; n0 = p0; n1 = p1;
    }
#undef LDX

    __syncthreads();

    // Phase 2: thread -> (batch b = tid>>2, quadrant q = tid&3)
    {
        const int b = tid >> 2;                // 0..63
        const int q = tid & 3;
        const float4* row =
            reinterpret_cast<const float4*>(&sred[b >> 3][b & 7][q][0]);
        float4 s4 = make_float4(0.f, 0.f, 0.f, 0.f);
#pragma unroll
        for (int i = 0; i < 8; i++) {
            const float4 v = row[i];
            s4.x += v.x; s4.y += v.y; s4.z += v.z; s4.w += v.w;
        }
        const float s = (s4.x + s4.y) + (s4.z + s4.w);

        const int r = Ri - (q >> 1), c = Ci - (q & 1);
        if (r >= 0 && r < NKH && c >= 0 && c < NKW)
            atomicAdd(out + (size_t)b * NK + r * NKW + c, s);
    }
}

extern "C" void kernel_launch(void* const* d_in, const int* in_sizes, int n_in,
                              void* d_out, int out_size)
{
    const float* x      = (const float*)d_in[0];   // (64,1,512,512) fp32
    const float* weight = (const float*)d_in[1];   // (1024,1024)    fp32
    const float* bias   = (const float*)d_in[2];   // (1024,)        fp32
    float*       out    = (float*)d_out;           // (64,32,32)     fp32

    bslc_init<<<(BATCH * NK) / (256 * 4), 256>>>(
        (const float4*)bias, (float4*)out);

    bslc_main<<<NC * NC, 256>>>(x, weight, out);
}